// round 5
// baseline (speedup 1.0000x reference)
#include <cuda_runtime.h>
#include <cuda_bf16.h>
#include <cstdint>

// out[b] = V @ rho[b] @ V^T,  V = kron(uc[:,2:4], W),  W = kron(ux, uy) (64x64)
// M_cd = W @ rho_cd @ W^T computed in place in one 128x128 smem buffer via
// four 8x8 mode contractions (A-y, A-x over columns; B-y, B-x over rows),
// all math in packed f32x2. uc-expansion fused into the store epilogue.

#define RS 132   // smem row stride in floats: float4-aligned, ≡4 mod 32 banks

typedef unsigned long long ull;

__device__ __forceinline__ ull pk(float lo, float hi) {
    ull r; asm("mov.b64 %0, {%1,%2};" : "=l"(r) : "f"(lo), "f"(hi)); return r;
}
__device__ __forceinline__ void upk(ull v, float& lo, float& hi) {
    asm("mov.b64 {%0,%1}, %2;" : "=f"(lo), "=f"(hi) : "l"(v));
}
__device__ __forceinline__ ull fma2(ull a, ull b, ull c) {
    ull d; asm("fma.rn.f32x2 %0, %1, %2, %3;" : "=l"(d) : "l"(a), "l"(b), "l"(c)); return d;
}
__device__ __forceinline__ ull mul2(ull a, ull b) {
    ull d; asm("mul.rn.f32x2 %0, %1, %2;" : "=l"(d) : "l"(a), "l"(b)); return d;
}

// 8x8 contraction on packed pair-vector z2[8] with duplicated coeffs cd[64].
__device__ __forceinline__ void contract8(const ull* __restrict__ cd,
                                          const ull z2[8], ull acc[8])
{
    #pragma unroll
    for (int o = 0; o < 8; o++) {
        ull a = mul2(cd[o * 8 + 0], z2[0]);
        #pragma unroll
        for (int k = 1; k < 8; k++) a = fma2(cd[o * 8 + k], z2[k], a);
        acc[o] = a;
    }
}

extern "C" __global__ void __launch_bounds__(512, 2)
qconv_kernel(const float* __restrict__ rho,
             const float* __restrict__ ux,
             const float* __restrict__ uy,
             const float* __restrict__ uc,
             float* __restrict__ out)
{
    extern __shared__ float s_m[];          // 128 * RS floats
    __shared__ ull s_uyd[64], s_uxd[64];    // duplicated-pair coefficients
    __shared__ float s_uc[16];

    const int b = blockIdx.x;
    const int t = threadIdx.x;

    if (t < 64) {
        float vx = ux[t], vy = uy[t];
        s_uxd[t] = pk(vx, vx);
        s_uyd[t] = pk(vy, vy);
    } else if (t < 80) {
        s_uc[t - 64] = uc[t - 64];
    }

    // ---- load rho[b]: 4096 float4, conflict-free smem stores ----
    {
        const float4* g = (const float4*)(rho + (size_t)b * 16384);
        #pragma unroll
        for (int i = 0; i < 8; i++) {
            int e4 = t + i * 512;           // 0..4095
            float4 v = g[e4];
            int r  = e4 >> 5;
            int c4 = e4 & 31;
            *(float4*)(s_m + r * RS + c4 * 4) = v;
        }
    }
    __syncthreads();

    // ---- A-y: contract ky with uy (columns). Pair = two kx halves of 16 contiguous floats.
    #pragma unroll
    for (int it = 0; it < 2; it++) {
        int u   = t + it * 512;             // 0..1023
        int row = u & 127;
        int kxp = u >> 7;                   // 0..7
        float* p = s_m + row * RS + kxp * 16;

        float4 v0 = *(float4*)(p);
        float4 v1 = *(float4*)(p + 4);
        float4 v2 = *(float4*)(p + 8);
        float4 v3 = *(float4*)(p + 12);

        ull z2[8];
        z2[0] = pk(v0.x, v2.x); z2[1] = pk(v0.y, v2.y);
        z2[2] = pk(v0.z, v2.z); z2[3] = pk(v0.w, v2.w);
        z2[4] = pk(v1.x, v3.x); z2[5] = pk(v1.y, v3.y);
        z2[6] = pk(v1.z, v3.z); z2[7] = pk(v1.w, v3.w);

        ull acc[8];
        contract8(s_uyd, z2, acc);

        float lo[8], hi[8];
        #pragma unroll
        for (int o = 0; o < 8; o++) upk(acc[o], lo[o], hi[o]);
        *(float4*)(p)      = make_float4(lo[0], lo[1], lo[2], lo[3]);
        *(float4*)(p + 4)  = make_float4(lo[4], lo[5], lo[6], lo[7]);
        *(float4*)(p + 8)  = make_float4(hi[0], hi[1], hi[2], hi[3]);
        *(float4*)(p + 12) = make_float4(hi[4], hi[5], hi[6], hi[7]);
    }
    __syncthreads();

    // ---- A-x: contract kx with ux (columns). Pair = adjacent ky (float2 loads, stride 8).
    #pragma unroll
    for (int it = 0; it < 2; it++) {
        int u    = t + it * 512;
        int row  = u & 127;
        int rest = u >> 7;                  // 0..7
        int kyp  = rest & 3;
        int cb   = rest >> 2;
        float* p = s_m + row * RS + cb * 64 + kyp * 2;

        ull z2[8];
        #pragma unroll
        for (int k = 0; k < 8; k++) z2[k] = *(ull*)(p + k * 8);

        ull acc[8];
        contract8(s_uxd, z2, acc);

        #pragma unroll
        for (int o = 0; o < 8; o++) *(ull*)(p + o * 8) = acc[o];
    }
    __syncthreads();

    // ---- B-y: contract ky with uy (rows). Pair = adjacent columns (float2, stride RS).
    #pragma unroll
    for (int it = 0; it < 2; it++) {
        int u    = t + it * 512;
        int colp = u & 63;
        int rg   = u >> 6;                  // 0..15
        float* p = s_m + rg * 8 * RS + colp * 2;

        ull z2[8];
        #pragma unroll
        for (int k = 0; k < 8; k++) z2[k] = *(ull*)(p + k * RS);

        ull acc[8];
        contract8(s_uyd, z2, acc);

        #pragma unroll
        for (int o = 0; o < 8; o++) *(ull*)(p + o * RS) = acc[o];
    }
    __syncthreads();

    // ---- B-x: contract kx with ux (rows). Pair = adjacent columns (float2, stride 8*RS).
    #pragma unroll
    for (int it = 0; it < 2; it++) {
        int u    = t + it * 512;
        int colp = u & 63;
        int rest = u >> 6;                  // 0..15
        int ky   = rest & 7;
        int cbr  = rest >> 3;
        float* p = s_m + (cbr * 64 + ky) * RS + colp * 2;

        ull z2[8];
        #pragma unroll
        for (int k = 0; k < 8; k++) z2[k] = *(ull*)(p + k * 8 * RS);

        ull acc[8];
        contract8(s_uxd, z2, acc);

        #pragma unroll
        for (int o = 0; o < 8; o++) *(ull*)(p + o * 8 * RS) = acc[o];
    }
    __syncthreads();

    // ---- Epilogue: uc-expand 128x128 -> 256x256, packed math, coalesced 128-bit stores.
    {
        ull a2[4], b2[4];
        #pragma unroll
        for (int f = 0; f < 4; f++) {
            float af = s_uc[f * 4 + 2], bf = s_uc[f * 4 + 3];
            a2[f] = pk(af, af);
            b2[f] = pk(bf, bf);
        }
        float* ob = out + (size_t)b * 65536;

        #pragma unroll
        for (int it = 0; it < 2; it++) {
            int pos = t + it * 512;         // 0..1023
            int i   = pos >> 4;             // 0..63
            int j4  = pos & 15;
            const float* base = s_m + i * RS + j4 * 4;

            float4 m00 = *(const float4*)(base);
            float4 m01 = *(const float4*)(base + 64);
            float4 m10 = *(const float4*)(base + 64 * RS);
            float4 m11 = *(const float4*)(base + 64 * RS + 64);

            ull u00a = pk(m00.x, m00.y), u00b = pk(m00.z, m00.w);
            ull u01a = pk(m01.x, m01.y), u01b = pk(m01.z, m01.w);
            ull u10a = pk(m10.x, m10.y), u10b = pk(m10.z, m10.w);
            ull u11a = pk(m11.x, m11.y), u11b = pk(m11.z, m11.w);

            #pragma unroll
            for (int f = 0; f < 4; f++) {
                ull r0a = fma2(a2[f], u00a, mul2(b2[f], u10a));
                ull r0b = fma2(a2[f], u00b, mul2(b2[f], u10b));
                ull r1a = fma2(a2[f], u01a, mul2(b2[f], u11a));
                ull r1b = fma2(a2[f], u01b, mul2(b2[f], u11b));
                float* orow = ob + (size_t)(f * 64 + i) * 256 + j4 * 4;
                #pragma unroll
                for (int g = 0; g < 4; g++) {
                    ull va = fma2(a2[g], r0a, mul2(b2[g], r1a));
                    ull vb = fma2(a2[g], r0b, mul2(b2[g], r1b));
                    ulonglong2 st; st.x = va; st.y = vb;
                    *(ulonglong2*)(orow + g * 64) = st;
                }
            }
        }
    }
}

extern "C" void kernel_launch(void* const* d_in, const int* in_sizes, int n_in,
                              void* d_out, int out_size)
{
    const float* rho = (const float*)d_in[0];
    const float* ux  = (const float*)d_in[1];
    const float* uy  = (const float*)d_in[2];
    const float* uc  = (const float*)d_in[3];
    float* out = (float*)d_out;

    const int smem_bytes = 128 * RS * (int)sizeof(float);  // 67584
    cudaFuncSetAttribute(qconv_kernel,
                         cudaFuncAttributeMaxDynamicSharedMemorySize, smem_bytes);

    qconv_kernel<<<256, 512, smem_bytes>>>(rho, ux, uy, uc, out);
}

// round 6
// speedup vs baseline: 1.8711x; 1.8711x over previous
#include <cuda_runtime.h>
#include <cuda_bf16.h>
#include <cstdint>

// out[b] = V @ rho[b] @ V^T,  V = kron(uc[:,2:4], W),  W = kron(ux, uy) (64x64)
// M_cd = W @ rho_cd @ W^T computed in place in one 128x128 smem buffer via
// four 8x8 mode contractions (A-y, A-x over columns; B-y, B-x over rows),
// all math in packed f32x2. uc-expansion fused into the store epilogue.
//
// 256 threads/CTA, __launch_bounds__(256,2): 128-reg budget -> no spills
// (R4's 512-thread variant capped at 64 regs and spilled ~300MB to local).

#define RS 132   // smem row stride in floats: float4-aligned, ≡4 mod 32 banks

typedef unsigned long long ull;

__device__ __forceinline__ ull pk(float lo, float hi) {
    ull r; asm("mov.b64 %0, {%1,%2};" : "=l"(r) : "f"(lo), "f"(hi)); return r;
}
__device__ __forceinline__ void upk(ull v, float& lo, float& hi) {
    asm("mov.b64 {%0,%1}, %2;" : "=f"(lo), "=f"(hi) : "l"(v));
}
__device__ __forceinline__ ull fma2(ull a, ull b, ull c) {
    ull d; asm("fma.rn.f32x2 %0, %1, %2, %3;" : "=l"(d) : "l"(a), "l"(b), "l"(c)); return d;
}
__device__ __forceinline__ ull mul2(ull a, ull b) {
    ull d; asm("mul.rn.f32x2 %0, %1, %2;" : "=l"(d) : "l"(a), "l"(b)); return d;
}

// 8x8 contraction on packed pair-vector z2[8] with duplicated coeffs cd[64].
__device__ __forceinline__ void contract8(const ull* __restrict__ cd,
                                          const ull z2[8], ull acc[8])
{
    #pragma unroll
    for (int o = 0; o < 8; o++) {
        ull a = mul2(cd[o * 8 + 0], z2[0]);
        #pragma unroll
        for (int k = 1; k < 8; k++) a = fma2(cd[o * 8 + k], z2[k], a);
        acc[o] = a;
    }
}

extern "C" __global__ void __launch_bounds__(256, 2)
qconv_kernel(const float* __restrict__ rho,
             const float* __restrict__ ux,
             const float* __restrict__ uy,
             const float* __restrict__ uc,
             float* __restrict__ out)
{
    extern __shared__ float s_m[];          // 128 * RS floats
    __shared__ ull s_uyd[64], s_uxd[64];    // duplicated-pair coefficients
    __shared__ float s_uc[16];

    const int b = blockIdx.x;
    const int t = threadIdx.x;

    if (t < 64) {
        float vx = ux[t], vy = uy[t];
        s_uxd[t] = pk(vx, vx);
        s_uyd[t] = pk(vy, vy);
    } else if (t < 80) {
        s_uc[t - 64] = uc[t - 64];
    }

    // ---- load rho[b]: 4096 float4, conflict-free smem stores ----
    {
        const float4* g = (const float4*)(rho + (size_t)b * 16384);
        #pragma unroll
        for (int i = 0; i < 16; i++) {
            int e4 = t + i * 256;           // 0..4095
            float4 v = g[e4];
            int r  = e4 >> 5;
            int c4 = e4 & 31;
            *(float4*)(s_m + r * RS + c4 * 4) = v;
        }
    }
    __syncthreads();

    // ---- A-y: contract ky with uy (columns). Unit = 16 contiguous floats
    //      (kx pair {2p,2p+1} x ky 0..7); lanes pair the two kx halves.
    #pragma unroll
    for (int it = 0; it < 4; it++) {
        int u   = t + it * 256;             // 0..1023
        int row = u & 127;
        int kxp = u >> 7;                   // 0..7
        float* p = s_m + row * RS + kxp * 16;

        float4 v0 = *(float4*)(p);
        float4 v1 = *(float4*)(p + 4);
        float4 v2 = *(float4*)(p + 8);
        float4 v3 = *(float4*)(p + 12);

        ull z2[8];
        z2[0] = pk(v0.x, v2.x); z2[1] = pk(v0.y, v2.y);
        z2[2] = pk(v0.z, v2.z); z2[3] = pk(v0.w, v2.w);
        z2[4] = pk(v1.x, v3.x); z2[5] = pk(v1.y, v3.y);
        z2[6] = pk(v1.z, v3.z); z2[7] = pk(v1.w, v3.w);

        ull acc[8];
        contract8(s_uyd, z2, acc);

        float lo[8], hi[8];
        #pragma unroll
        for (int o = 0; o < 8; o++) upk(acc[o], lo[o], hi[o]);
        *(float4*)(p)      = make_float4(lo[0], lo[1], lo[2], lo[3]);
        *(float4*)(p + 4)  = make_float4(lo[4], lo[5], lo[6], lo[7]);
        *(float4*)(p + 8)  = make_float4(hi[0], hi[1], hi[2], hi[3]);
        *(float4*)(p + 12) = make_float4(hi[4], hi[5], hi[6], hi[7]);
    }
    __syncthreads();

    // ---- A-x: contract kx with ux (columns). Pair = adjacent ky (float2 loads, stride 8).
    #pragma unroll
    for (int it = 0; it < 4; it++) {
        int u    = t + it * 256;
        int row  = u & 127;
        int rest = u >> 7;                  // 0..7
        int kyp  = rest & 3;
        int cb   = rest >> 2;
        float* p = s_m + row * RS + cb * 64 + kyp * 2;

        ull z2[8];
        #pragma unroll
        for (int k = 0; k < 8; k++) z2[k] = *(ull*)(p + k * 8);

        ull acc[8];
        contract8(s_uxd, z2, acc);

        #pragma unroll
        for (int o = 0; o < 8; o++) *(ull*)(p + o * 8) = acc[o];
    }
    __syncthreads();

    // ---- B-y: contract ky with uy (rows). Pair = adjacent columns (float2, stride RS).
    #pragma unroll
    for (int it = 0; it < 4; it++) {
        int u    = t + it * 256;
        int colp = u & 63;
        int rg   = u >> 6;                  // 0..15
        float* p = s_m + rg * 8 * RS + colp * 2;

        ull z2[8];
        #pragma unroll
        for (int k = 0; k < 8; k++) z2[k] = *(ull*)(p + k * RS);

        ull acc[8];
        contract8(s_uyd, z2, acc);

        #pragma unroll
        for (int o = 0; o < 8; o++) *(ull*)(p + o * RS) = acc[o];
    }
    __syncthreads();

    // ---- B-x: contract kx with ux (rows). Pair = adjacent columns (float2, stride 8*RS).
    #pragma unroll
    for (int it = 0; it < 4; it++) {
        int u    = t + it * 256;
        int colp = u & 63;
        int rest = u >> 6;                  // 0..15
        int ky   = rest & 7;
        int cbr  = rest >> 3;
        float* p = s_m + (cbr * 64 + ky) * RS + colp * 2;

        ull z2[8];
        #pragma unroll
        for (int k = 0; k < 8; k++) z2[k] = *(ull*)(p + k * 8 * RS);

        ull acc[8];
        contract8(s_uxd, z2, acc);

        #pragma unroll
        for (int o = 0; o < 8; o++) *(ull*)(p + o * 8 * RS) = acc[o];
    }
    __syncthreads();

    // ---- Epilogue: uc-expand 128x128 -> 256x256, packed math, coalesced 128-bit stores.
    {
        ull a2[4], b2[4];
        #pragma unroll
        for (int f = 0; f < 4; f++) {
            float af = s_uc[f * 4 + 2], bf = s_uc[f * 4 + 3];
            a2[f] = pk(af, af);
            b2[f] = pk(bf, bf);
        }
        float* ob = out + (size_t)b * 65536;

        #pragma unroll
        for (int it = 0; it < 4; it++) {
            int pos = t + it * 256;         // 0..1023
            int i   = pos >> 4;             // 0..63
            int j4  = pos & 15;
            const float* base = s_m + i * RS + j4 * 4;

            float4 m00 = *(const float4*)(base);
            float4 m01 = *(const float4*)(base + 64);
            float4 m10 = *(const float4*)(base + 64 * RS);
            float4 m11 = *(const float4*)(base + 64 * RS + 64);

            ull u00a = pk(m00.x, m00.y), u00b = pk(m00.z, m00.w);
            ull u01a = pk(m01.x, m01.y), u01b = pk(m01.z, m01.w);
            ull u10a = pk(m10.x, m10.y), u10b = pk(m10.z, m10.w);
            ull u11a = pk(m11.x, m11.y), u11b = pk(m11.z, m11.w);

            #pragma unroll
            for (int f = 0; f < 4; f++) {
                ull r0a = fma2(a2[f], u00a, mul2(b2[f], u10a));
                ull r0b = fma2(a2[f], u00b, mul2(b2[f], u10b));
                ull r1a = fma2(a2[f], u01a, mul2(b2[f], u11a));
                ull r1b = fma2(a2[f], u01b, mul2(b2[f], u11b));
                float* orow = ob + (size_t)(f * 64 + i) * 256 + j4 * 4;
                #pragma unroll
                for (int g = 0; g < 4; g++) {
                    ull va = fma2(a2[g], r0a, mul2(b2[g], r1a));
                    ull vb = fma2(a2[g], r0b, mul2(b2[g], r1b));
                    ulonglong2 st; st.x = va; st.y = vb;
                    *(ulonglong2*)(orow + g * 64) = st;
                }
            }
        }
    }
}

extern "C" void kernel_launch(void* const* d_in, const int* in_sizes, int n_in,
                              void* d_out, int out_size)
{
    const float* rho = (const float*)d_in[0];
    const float* ux  = (const float*)d_in[1];
    const float* uy  = (const float*)d_in[2];
    const float* uc  = (const float*)d_in[3];
    float* out = (float*)d_out;

    const int smem_bytes = 128 * RS * (int)sizeof(float);  // 67584
    cudaFuncSetAttribute(qconv_kernel,
                         cudaFuncAttributeMaxDynamicSharedMemorySize, smem_bytes);

    qconv_kernel<<<256, 256, smem_bytes>>>(rho, ux, uy, uc, out);
}

// round 8
// speedup vs baseline: 4.1519x; 2.2190x over previous
#include <cuda_runtime.h>
#include <cuda_bf16.h>
#include <cstdint>

// out[b] = V @ rho[b] @ V^T,  V = kron(uc[:,2:4], W),  W = kron(ux, uy) (64x64)
// One 128x128 smem buffer transformed in place by four 8x8 mode contractions
// (A-y, A-x along columns; B-y, B-x along rows); uc-expansion fused into stores.
//
// Key change vs prior rounds: each pass caches the full 8x8 coefficient matrix
// (64 floats) in REGISTERS (compile-time indexed), so every FMA is register-only
// FFMA — no per-FMA shared-memory coefficient loads (R3/R6's hidden cost).

#define RS 132   // smem row stride in floats: float4-aligned, ≡4 mod 32 banks

__device__ __forceinline__ void cache64(float* __restrict__ c,
                                        const float* __restrict__ s)
{
    #pragma unroll
    for (int k = 0; k < 16; k++) {
        float4 v = *(const float4*)(s + k * 4);   // broadcast LDS.128
        c[k * 4 + 0] = v.x; c[k * 4 + 1] = v.y;
        c[k * 4 + 2] = v.z; c[k * 4 + 3] = v.w;
    }
}

extern "C" __global__ void __launch_bounds__(256, 2)
qconv_kernel(const float* __restrict__ rho,
             const float* __restrict__ ux,
             const float* __restrict__ uy,
             const float* __restrict__ uc,
             float* __restrict__ out)
{
    extern __shared__ float s_m[];          // 128 * RS floats (67.5 KB)
    __shared__ float s_ux[64], s_uy[64], s_uc[16];

    const int b = blockIdx.x;
    const int t = threadIdx.x;

    if (t < 64)      { s_ux[t] = ux[t]; s_uy[t] = uy[t]; }
    else if (t < 80) { s_uc[t - 64] = uc[t - 64]; }

    // ---- load rho[b]: 4096 float4, conflict-free ----
    {
        const float4* g = (const float4*)(rho + (size_t)b * 16384);
        #pragma unroll
        for (int i = 0; i < 16; i++) {
            int e4 = t + i * 256;           // 0..4095
            float4 v = g[e4];
            int r  = e4 >> 5;
            int c4 = e4 & 31;
            *(float4*)(s_m + r * RS + c4 * 4) = v;
        }
    }
    __syncthreads();

    // ---- A-y: contract ky with uy along columns.
    //      Unit = 8 contiguous floats (row, group g = cb*8+kx). 2048 units, 8/thread.
    {
        float cy[64]; cache64(cy, s_uy);
        #pragma unroll
        for (int i = 0; i < 8; i++) {
            int u   = t + i * 256;
            int row = u & 127;
            int g   = u >> 7;               // 0..15
            float* p = s_m + row * RS + g * 8;
            float4 a = *(float4*)p;
            float4 c = *(float4*)(p + 4);
            float v[8] = { a.x, a.y, a.z, a.w, c.x, c.y, c.z, c.w };
            float o[8];
            #pragma unroll
            for (int iy = 0; iy < 8; iy++) {
                float acc = cy[iy * 8] * v[0];
                #pragma unroll
                for (int k = 1; k < 8; k++) acc = fmaf(cy[iy * 8 + k], v[k], acc);
                o[iy] = acc;
            }
            *(float4*)p       = make_float4(o[0], o[1], o[2], o[3]);
            *(float4*)(p + 4) = make_float4(o[4], o[5], o[6], o[7]);
        }
    }
    __syncthreads();

    // ---- A-x: contract kx with ux along columns.
    //      Unit = ky-pair column (row, cb, kyp): float2 loads stride 8. 1024 units, 4/thread.
    {
        float cx[64]; cache64(cx, s_ux);
        #pragma unroll
        for (int i = 0; i < 4; i++) {
            int u   = t + i * 256;          // 0..1023
            int kyp = u & 3;
            int cb  = (u >> 2) & 1;
            int row = u >> 3;               // 0..127
            float* p = s_m + row * RS + cb * 64 + kyp * 2;
            float2 v[8];
            #pragma unroll
            for (int k = 0; k < 8; k++) v[k] = *(float2*)(p + k * 8);
            float2 o[8];
            #pragma unroll
            for (int ix = 0; ix < 8; ix++) {
                float ax = cx[ix * 8] * v[0].x;
                float ay = cx[ix * 8] * v[0].y;
                #pragma unroll
                for (int k = 1; k < 8; k++) {
                    ax = fmaf(cx[ix * 8 + k], v[k].x, ax);
                    ay = fmaf(cx[ix * 8 + k], v[k].y, ay);
                }
                o[ix] = make_float2(ax, ay);
            }
            #pragma unroll
            for (int ix = 0; ix < 8; ix++) *(float2*)(p + ix * 8) = o[ix];
        }
    }
    __syncthreads();

    // ---- B-y: contract ky with uy along rows.
    //      Unit = col-pair (colp, rg): float2 loads stride RS. 1024 units, 4/thread.
    {
        float cy[64]; cache64(cy, s_uy);
        #pragma unroll
        for (int i = 0; i < 4; i++) {
            int u    = t + i * 256;
            int colp = u & 63;
            int rg   = u >> 6;              // 0..15
            float* p = s_m + rg * 8 * RS + colp * 2;
            float2 v[8];
            #pragma unroll
            for (int k = 0; k < 8; k++) v[k] = *(float2*)(p + k * RS);
            float2 o[8];
            #pragma unroll
            for (int iy = 0; iy < 8; iy++) {
                float ax = cy[iy * 8] * v[0].x;
                float ay = cy[iy * 8] * v[0].y;
                #pragma unroll
                for (int k = 1; k < 8; k++) {
                    ax = fmaf(cy[iy * 8 + k], v[k].x, ax);
                    ay = fmaf(cy[iy * 8 + k], v[k].y, ay);
                }
                o[iy] = make_float2(ax, ay);
            }
            #pragma unroll
            for (int iy = 0; iy < 8; iy++) *(float2*)(p + iy * RS) = o[iy];
        }
    }
    __syncthreads();

    // ---- B-x: contract kx with ux along rows.
    //      Unit = col-pair (colp, cbr, ky): float2 loads stride 8*RS. 1024 units, 4/thread.
    {
        float cx[64]; cache64(cx, s_ux);
        #pragma unroll
        for (int i = 0; i < 4; i++) {
            int u    = t + i * 256;
            int colp = u & 63;
            int rest = u >> 6;              // 0..15
            int ky   = rest & 7;
            int cbr  = rest >> 3;
            float* p = s_m + (cbr * 64 + ky) * RS + colp * 2;
            float2 v[8];
            #pragma unroll
            for (int k = 0; k < 8; k++) v[k] = *(float2*)(p + k * 8 * RS);
            float2 o[8];
            #pragma unroll
            for (int ix = 0; ix < 8; ix++) {
                float ax = cx[ix * 8] * v[0].x;
                float ay = cx[ix * 8] * v[0].y;
                #pragma unroll
                for (int k = 1; k < 8; k++) {
                    ax = fmaf(cx[ix * 8 + k], v[k].x, ax);
                    ay = fmaf(cx[ix * 8 + k], v[k].y, ay);
                }
                o[ix] = make_float2(ax, ay);
            }
            #pragma unroll
            for (int ix = 0; ix < 8; ix++) *(float2*)(p + ix * 8 * RS) = o[ix];
        }
    }
    __syncthreads();

    // ---- Epilogue: uc-expand 128x128 -> 256x256, coalesced float4 stores (R3-proven).
    {
        const float ga[4] = { s_uc[2], s_uc[6], s_uc[10], s_uc[14] };
        const float gb[4] = { s_uc[3], s_uc[7], s_uc[11], s_uc[15] };
        float* ob = out + (size_t)b * 65536;

        #pragma unroll
        for (int it = 0; it < 4; it++) {
            int pos = t + it * 256;         // 0..1023
            int i   = pos >> 4;             // 0..63
            int j   = (pos & 15) * 4;       // 0..60

            const float* p00 = s_m + i * RS + j;
            const float* p01 = p00 + 64;
            const float* p10 = p00 + 64 * RS;
            const float* p11 = p10 + 64;

            float4 m00 = *(const float4*)p00;
            float4 m01 = *(const float4*)p01;
            float4 m10 = *(const float4*)p10;
            float4 m11 = *(const float4*)p11;

            #pragma unroll
            for (int f = 0; f < 4; f++) {
                const float af = ga[f], bf = gb[f];
                float r0[4], r1[4];
                r0[0] = fmaf(af, m00.x, bf * m10.x);
                r0[1] = fmaf(af, m00.y, bf * m10.y);
                r0[2] = fmaf(af, m00.z, bf * m10.z);
                r0[3] = fmaf(af, m00.w, bf * m10.w);
                r1[0] = fmaf(af, m01.x, bf * m11.x);
                r1[1] = fmaf(af, m01.y, bf * m11.y);
                r1[2] = fmaf(af, m01.z, bf * m11.z);
                r1[3] = fmaf(af, m01.w, bf * m11.w);
                float* orow = ob + (size_t)(f * 64 + i) * 256 + j;
                #pragma unroll
                for (int g = 0; g < 4; g++) {
                    const float ag = ga[g], bg = gb[g];
                    float4 v;
                    v.x = fmaf(ag, r0[0], bg * r1[0]);
                    v.y = fmaf(ag, r0[1], bg * r1[1]);
                    v.z = fmaf(ag, r0[2], bg * r1[2]);
                    v.w = fmaf(ag, r0[3], bg * r1[3]);
                    *(float4*)(orow + g * 64) = v;
                }
            }
        }
    }
}

extern "C" void kernel_launch(void* const* d_in, const int* in_sizes, int n_in,
                              void* d_out, int out_size)
{
    const float* rho = (const float*)d_in[0];
    const float* ux  = (const float*)d_in[1];
    const float* uy  = (const float*)d_in[2];
    const float* uc  = (const float*)d_in[3];
    float* out = (float*)d_out;

    const int smem_bytes = 128 * RS * (int)sizeof(float);  // 67584
    cudaFuncSetAttribute(qconv_kernel,
                         cudaFuncAttributeMaxDynamicSharedMemorySize, smem_bytes);

    qconv_kernel<<<256, 256, smem_bytes>>>(rho, ux, uy, uc, out);
}

// round 11
// speedup vs baseline: 4.1944x; 1.0102x over previous
#include <cuda_runtime.h>
#include <cuda_bf16.h>
#include <cstdint>

// out[b] = V @ rho[b] @ V^T,  V = kron(uc[:,2:4], W),  W = kron(ux, uy) (64x64)
// One 128x128 smem buffer transformed in place by four 8x8 mode contractions;
// uc-expansion fused into the store epilogue.
//
// R9: A-y fused with the global load (regs, no staging, no first barrier);
// all smem passes use float4 units with conflict-free lane maps (RS=132,
// quad-bank = 33*row + ... verified distinct per 8-lane phase); coefficients
// register-cached. 4 barriers total.

#define RS 132   // row stride (floats): float4-aligned; 33 quad-banks/row

__device__ __forceinline__ void cache64(float* __restrict__ c,
                                        const float* __restrict__ s)
{
    #pragma unroll
    for (int k = 0; k < 16; k++) {
        float4 v = *(const float4*)(s + k * 4);   // broadcast LDS.128
        c[k * 4 + 0] = v.x; c[k * 4 + 1] = v.y;
        c[k * 4 + 2] = v.z; c[k * 4 + 3] = v.w;
    }
}

extern "C" __global__ void __launch_bounds__(256, 2)
qconv_kernel(const float* __restrict__ rho,
             const float* __restrict__ ux,
             const float* __restrict__ uy,
             const float* __restrict__ uc,
             float* __restrict__ out)
{
    extern __shared__ float s_m[];          // 128 * RS floats (67.5 KB)
    __shared__ float s_ux[64], s_uy[64], s_uc[16];

    const int b = blockIdx.x;
    const int t = threadIdx.x;

    if (t < 64)      { s_ux[t] = ux[t]; s_uy[t] = uy[t]; }
    else if (t < 80) { s_uc[t - 64] = uc[t - 64]; }
    // (s_ux/s_uy/s_uc are first read AFTER the barrier below — no race.)

    // ---- A-y fused with global load: thread owns (row, half) = 64 contiguous
    //      floats; contract ky with uy (coeffs via __ldg, L1-broadcast);
    //      results written once to smem (STS.128, conflict-free).
    {
        const int row  = t >> 1;
        const int half = t & 1;
        const float4* gp = (const float4*)(rho + (size_t)b * 16384 + row * 128 + half * 64);

        float v[64];
        #pragma unroll
        for (int j = 0; j < 16; j++) {
            float4 x = __ldg(gp + j);
            v[4*j+0] = x.x; v[4*j+1] = x.y; v[4*j+2] = x.z; v[4*j+3] = x.w;
        }

        float* op = s_m + row * RS + half * 64;
        #pragma unroll
        for (int h = 0; h < 2; h++) {       // coefficient half-sweep (iy = h*4..h*4+3)
            float cy[32];
            #pragma unroll
            for (int j = 0; j < 8; j++) {
                float4 x = __ldg((const float4*)uy + h * 8 + j);
                cy[4*j+0] = x.x; cy[4*j+1] = x.y; cy[4*j+2] = x.z; cy[4*j+3] = x.w;
            }
            #pragma unroll
            for (int gl = 0; gl < 8; gl++) { // 8-float group within the half-row
                float o[4];
                #pragma unroll
                for (int iy = 0; iy < 4; iy++) {
                    float acc = cy[iy * 8] * v[gl * 8];
                    #pragma unroll
                    for (int k = 1; k < 8; k++)
                        acc = fmaf(cy[iy * 8 + k], v[gl * 8 + k], acc);
                    o[iy] = acc;
                }
                *(float4*)(op + gl * 8 + h * 4) = make_float4(o[0], o[1], o[2], o[3]);
            }
        }
    }
    __syncthreads();

    // ---- A-x: contract kx with ux along columns.
    //      Unit = (row, cb, kyq): 4 ky-cols x 8 kx; LDS.128 stride 8, conflict-free.
    {
        float cx[64]; cache64(cx, s_ux);
        #pragma unroll
        for (int i = 0; i < 2; i++) {
            int u    = t + i * 256;          // 0..511
            int row  = u & 127;
            int cb   = (u >> 7) & 1;
            int kyq  = u >> 8;
            float* p = s_m + row * RS + cb * 64 + kyq * 4;

            float4 v[8];
            #pragma unroll
            for (int k = 0; k < 8; k++) v[k] = *(float4*)(p + k * 8);
            #pragma unroll
            for (int ix = 0; ix < 8; ix++) {
                float4 o;
                o.x = cx[ix*8] * v[0].x; o.y = cx[ix*8] * v[0].y;
                o.z = cx[ix*8] * v[0].z; o.w = cx[ix*8] * v[0].w;
                #pragma unroll
                for (int k = 1; k < 8; k++) {
                    o.x = fmaf(cx[ix*8+k], v[k].x, o.x);
                    o.y = fmaf(cx[ix*8+k], v[k].y, o.y);
                    o.z = fmaf(cx[ix*8+k], v[k].z, o.z);
                    o.w = fmaf(cx[ix*8+k], v[k].w, o.w);
                }
                *(float4*)(p + ix * 8) = o;   // safe: v fully in regs
            }
        }
    }
    __syncthreads();

    // ---- B-y: contract ky with uy along rows.
    //      Unit = (colq, rg): 4 cols x 8 ky; LDS.128 stride RS, conflict-free.
    {
        float cy[64]; cache64(cy, s_uy);
        #pragma unroll
        for (int i = 0; i < 2; i++) {
            int u    = t + i * 256;
            int colq = u & 31;
            int rg   = u >> 5;               // 0..15
            float* p = s_m + rg * 8 * RS + colq * 4;

            float4 v[8];
            #pragma unroll
            for (int k = 0; k < 8; k++) v[k] = *(float4*)(p + k * RS);
            #pragma unroll
            for (int iy = 0; iy < 8; iy++) {
                float4 o;
                o.x = cy[iy*8] * v[0].x; o.y = cy[iy*8] * v[0].y;
                o.z = cy[iy*8] * v[0].z; o.w = cy[iy*8] * v[0].w;
                #pragma unroll
                for (int k = 1; k < 8; k++) {
                    o.x = fmaf(cy[iy*8+k], v[k].x, o.x);
                    o.y = fmaf(cy[iy*8+k], v[k].y, o.y);
                    o.z = fmaf(cy[iy*8+k], v[k].z, o.z);
                    o.w = fmaf(cy[iy*8+k], v[k].w, o.w);
                }
                *(float4*)(p + iy * RS) = o;
            }
        }
    }
    __syncthreads();

    // ---- B-x: contract kx with ux along rows.
    //      Unit = (colq, cbr, ky): 4 cols x 8 kx; LDS.128 stride 8*RS, conflict-free.
    {
        float cx[64]; cache64(cx, s_ux);
        #pragma unroll
        for (int i = 0; i < 2; i++) {
            int u    = t + i * 256;
            int colq = u & 31;
            int rest = u >> 5;               // 0..15
            int ky   = rest & 7;
            int cbr  = rest >> 3;
            float* p = s_m + (cbr * 64 + ky) * RS + colq * 4;

            float4 v[8];
            #pragma unroll
            for (int k = 0; k < 8; k++) v[k] = *(float4*)(p + k * 8 * RS);
            #pragma unroll
            for (int ix = 0; ix < 8; ix++) {
                float4 o;
                o.x = cx[ix*8] * v[0].x; o.y = cx[ix*8] * v[0].y;
                o.z = cx[ix*8] * v[0].z; o.w = cx[ix*8] * v[0].w;
                #pragma unroll
                for (int k = 1; k < 8; k++) {
                    o.x = fmaf(cx[ix*8+k], v[k].x, o.x);
                    o.y = fmaf(cx[ix*8+k], v[k].y, o.y);
                    o.z = fmaf(cx[ix*8+k], v[k].z, o.z);
                    o.w = fmaf(cx[ix*8+k], v[k].w, o.w);
                }
                *(float4*)(p + ix * 8 * RS) = o;
            }
        }
    }
    __syncthreads();

    // ---- Epilogue: uc-expand 128x128 -> 256x256, coalesced float4 stores.
    {
        const float ga[4] = { s_uc[2], s_uc[6], s_uc[10], s_uc[14] };
        const float gb[4] = { s_uc[3], s_uc[7], s_uc[11], s_uc[15] };
        float* ob = out + (size_t)b * 65536;

        #pragma unroll
        for (int it = 0; it < 4; it++) {
            int pos = t + it * 256;          // 0..1023
            int i   = pos >> 4;              // 0..63
            int j   = (pos & 15) * 4;        // 0..60

            const float* p00 = s_m + i * RS + j;
            float4 m00 = *(const float4*)p00;
            float4 m01 = *(const float4*)(p00 + 64);
            float4 m10 = *(const float4*)(p00 + 64 * RS);
            float4 m11 = *(const float4*)(p00 + 64 * RS + 64);

            #pragma unroll
            for (int f = 0; f < 4; f++) {
                const float af = ga[f], bf = gb[f];
                float r0[4], r1[4];
                r0[0] = fmaf(af, m00.x, bf * m10.x);
                r0[1] = fmaf(af, m00.y, bf * m10.y);
                r0[2] = fmaf(af, m00.z, bf * m10.z);
                r0[3] = fmaf(af, m00.w, bf * m10.w);
                r1[0] = fmaf(af, m01.x, bf * m11.x);
                r1[1] = fmaf(af, m01.y, bf * m11.y);
                r1[2] = fmaf(af, m01.z, bf * m11.z);
                r1[3] = fmaf(af, m01.w, bf * m11.w);
                float* orow = ob + (size_t)(f * 64 + i) * 256 + j;
                #pragma unroll
                for (int g = 0; g < 4; g++) {
                    const float ag = ga[g], bg = gb[g];
                    float4 v;
                    v.x = fmaf(ag, r0[0], bg * r1[0]);
                    v.y = fmaf(ag, r0[1], bg * r1[1]);
                    v.z = fmaf(ag, r0[2], bg * r1[2]);
                    v.w = fmaf(ag, r0[3], bg * r1[3]);
                    *(float4*)(orow + g * 64) = v;
                }
            }
        }
    }
}

extern "C" void kernel_launch(void* const* d_in, const int* in_sizes, int n_in,
                              void* d_out, int out_size)
{
    const float* rho = (const float*)d_in[0];
    const float* ux  = (const float*)d_in[1];
    const float* uy  = (const float*)d_in[2];
    const float* uc  = (const float*)d_in[3];
    float* out = (float*)d_out;

    const int smem_bytes = 128 * RS * (int)sizeof(float);  // 67584
    cudaFuncSetAttribute(qconv_kernel,
                         cudaFuncAttributeMaxDynamicSharedMemorySize, smem_bytes);

    qconv_kernel<<<256, 256, smem_bytes>>>(rho, ux, uy, uc, out);
}